// round 16
// baseline (speedup 1.0000x reference)
#include <cuda_runtime.h>
#include <cuda_fp16.h>
#include <cstdint>

// Problem constants
#define B_  4
#define T_  2048
#define C_  1024
#define H_  16
#define D_  64
#define M_  (B_ * T_)       // 8192 rows
#define QKV_N (3 * C_)      // 3072
#define NSM 148
#define GEMM_GRID (2 * NSM)   // 296 persistent CTAs (2/SM)

// ---------------------------------------------------------------------------
// Scratch (device globals; no runtime allocation allowed)
// ---------------------------------------------------------------------------
__device__ __half g_xh[(size_t)M_ * C_];
__device__ __half g_wqh[(size_t)QKV_N * C_];
__device__ __half g_wph[(size_t)C_ * C_];
__device__ __half g_qh[(size_t)M_ * QKV_N];
__device__ __half g_ch[(size_t)M_ * C_];

// ---------------------------------------------------------------------------
// PTX helpers (all non-arch-gated sm_80/sm_90 instructions)
// ---------------------------------------------------------------------------
__device__ __forceinline__ uint32_t smem_u32(const void* p) {
    uint32_t a;
    asm("{ .reg .u64 t; cvta.to.shared.u64 t, %1; cvt.u32.u64 %0, t; }"
        : "=r"(a) : "l"(p));
    return a;
}
__device__ __forceinline__ void cp_async16(uint32_t s, const void* g) {
    asm volatile("cp.async.cg.shared.global [%0], [%1], 16;"
                 :: "r"(s), "l"(g) : "memory");
}
#define CP_COMMIT() asm volatile("cp.async.commit_group;" ::: "memory")
#define CP_WAIT0()  asm volatile("cp.async.wait_group 0;" ::: "memory")
#define CP_WAIT1()  asm volatile("cp.async.wait_group 1;" ::: "memory")

__device__ __forceinline__ void ldm_x4(uint32_t* r, uint32_t a) {
    asm volatile("ldmatrix.sync.aligned.m8n8.x4.shared.b16 {%0,%1,%2,%3}, [%4];"
        : "=r"(r[0]), "=r"(r[1]), "=r"(r[2]), "=r"(r[3]) : "r"(a));
}
__device__ __forceinline__ void ldm_x4_t(uint32_t* r, uint32_t a) {
    asm volatile("ldmatrix.sync.aligned.m8n8.x4.trans.shared.b16 {%0,%1,%2,%3}, [%4];"
        : "=r"(r[0]), "=r"(r[1]), "=r"(r[2]), "=r"(r[3]) : "r"(a));
}
__device__ __forceinline__ void mma_f16(float* d, const uint32_t* a, const uint32_t* b) {
    asm volatile(
        "mma.sync.aligned.m16n8k16.row.col.f32.f16.f16.f32 "
        "{%0,%1,%2,%3}, {%4,%5,%6,%7}, {%8,%9}, {%0,%1,%2,%3};"
        : "+f"(d[0]), "+f"(d[1]), "+f"(d[2]), "+f"(d[3])
        : "r"(a[0]), "r"(a[1]), "r"(a[2]), "r"(a[3]), "r"(b[0]), "r"(b[1]));
}
// pack two f32 -> f16x2 ({hi -> upper16, lo -> lower16})
__device__ __forceinline__ uint32_t pack_f16x2(float hi, float lo) {
    uint32_t d;
    asm("cvt.rn.f16x2.f32 %0, %1, %2;" : "=r"(d) : "f"(hi), "f"(lo));
    return d;
}

// ---------------------------------------------------------------------------
// Fused prep: convert x, w_qkv, w_proj to fp16 in ONE launch.
// ---------------------------------------------------------------------------
#define NX_JOBS  (M_ * C_ / 4)
#define NWQ_JOBS (QKV_N * C_ / 4)
#define NWP_JOBS (C_ * C_ / 4)
#define PREP_JOBS (NX_JOBS + NWQ_JOBS + NWP_JOBS)

__global__ __launch_bounds__(256) void prep_f16(
    const float* __restrict__ x, const float* __restrict__ wq,
    const float* __restrict__ wp,
    __half* __restrict__ xh, __half* __restrict__ wqh, __half* __restrict__ wph)
{
    int i = blockIdx.x * blockDim.x + threadIdx.x;
    if (i >= PREP_JOBS) return;
    const float* src;
    __half* dst;
    int j;
    if (i < NX_JOBS)                    { src = x;  dst = xh;  j = i; }
    else if (i < NX_JOBS + NWQ_JOBS)    { src = wq; dst = wqh; j = i - NX_JOBS; }
    else                                { src = wp; dst = wph; j = i - NX_JOBS - NWQ_JOBS; }
    float4 v = reinterpret_cast<const float4*>(src)[j];
    reinterpret_cast<uint2*>(dst)[j] =
        make_uint2(pack_f16x2(v.y, v.x), pack_f16x2(v.w, v.z));
}

// ---------------------------------------------------------------------------
// Persistent mma.sync fp16 GEMM: C[M,N] = Ah[M,K] @ Bh[N,K]^T.
// Grid = 296 CTAs (2/SM, no tail waves); each CTA strides over 128x128 tiles.
// BK=64, 8 warps (2x4), warp tile 64x32, 2-stage cp.async pipeline.
// OUTH=true: write fp16; else fp32.
// ---------------------------------------------------------------------------
#define TILE_B  18432                   // 128 rows * 72 b16 * 2B
#define STAGE_B (2 * TILE_B)            // 36864
#define GEMM_SMEM (2 * STAGE_B)         // 73728 (x2 CTAs = 144KB <= 228KB)

template <bool OUTH>
__global__ __launch_bounds__(256, 2) void gemm_mma_f16(
    const __half* __restrict__ Ah, const __half* __restrict__ Bh,
    float* __restrict__ Cf, __half* __restrict__ Ch, int M, int N, int K)
{
    extern __shared__ char smc[];
    const uint32_t sbase = smem_u32(smc);
    const int tid = threadIdx.x;
    const int lid = tid & 31;
    const int wid = tid >> 5;
    const int wm  = wid >> 2;
    const int wn  = wid & 3;

    const int a_off = ((wm * 64 + (lid & 15)) * 72 + ((lid >> 4) * 8)) * 2;
    const int b_off = (((wn * 32 + (lid & 7) + ((lid >> 4) * 8)) * 72) +
                       (((lid >> 3) & 1) * 8)) * 2;
    const int NS  = K / 64;
    const int NTX = N / 128;
    const int NT  = NTX * (M / 128);

    for (int t = blockIdx.x; t < NT; t += gridDim.x) {
        const int n0 = (t % NTX) * 128;
        const int m0 = (t / NTX) * 128;

        float acc[4][4][4];
#pragma unroll
        for (int i = 0; i < 4; i++)
#pragma unroll
            for (int j = 0; j < 4; j++)
#pragma unroll
                for (int q = 0; q < 4; q++) acc[i][j][q] = 0.f;

#define ISSUE_STAGE(S)                                                          \
    do {                                                                        \
        const int _kc = (S) * 64;                                               \
        const uint32_t _sb = sbase + ((S) & 1) * STAGE_B;                       \
        _Pragma("unroll")                                                       \
        for (int _r = 0; _r < 4; _r++) {                                        \
            const int _c   = tid + _r * 256;                                    \
            const int _row = _c >> 3;                                           \
            const int _c8  = (_c & 7) * 8;                                      \
            const uint32_t _so = _sb + (uint32_t)((_row * 72 + _c8) * 2);       \
            cp_async16(_so,          Ah + (size_t)(m0 + _row) * K + _kc + _c8); \
            cp_async16(_so + TILE_B, Bh + (size_t)(n0 + _row) * K + _kc + _c8); \
        }                                                                       \
        CP_COMMIT();                                                            \
    } while (0)

        ISSUE_STAGE(0);

        for (int s = 0; s < NS; s++) {
            CP_WAIT0();
            __syncthreads();
            if (s + 1 < NS) ISSUE_STAGE(s + 1);

            const uint32_t sb = sbase + (s & 1) * STAGE_B;
#pragma unroll
            for (int ks = 0; ks < 4; ks++) {
                uint32_t ah[4][4], b01[4], b23[4];
#pragma unroll
                for (int mi = 0; mi < 4; mi++) {
                    const uint32_t ao = sb + (uint32_t)(a_off +
                        (mi * 16 * 72 + ks * 16) * 2);
                    ldm_x4(ah[mi], ao);
                }
                {
                    const uint32_t bo = sb + TILE_B +
                        (uint32_t)(b_off + (ks * 16) * 2);
                    ldm_x4(b01, bo);
                    ldm_x4(b23, bo + 16 * 72 * 2);
                }
#pragma unroll
                for (int mi = 0; mi < 4; mi++) {
                    mma_f16(acc[mi][0], ah[mi], &b01[0]);
                    mma_f16(acc[mi][1], ah[mi], &b01[2]);
                    mma_f16(acc[mi][2], ah[mi], &b23[0]);
                    mma_f16(acc[mi][3], ah[mi], &b23[2]);
                }
            }
        }
#undef ISSUE_STAGE

#pragma unroll
        for (int mi = 0; mi < 4; mi++)
#pragma unroll
            for (int ni = 0; ni < 4; ni++) {
                const int row = m0 + wm * 64 + mi * 16 + (lid >> 2);
                const int col = n0 + wn * 32 + ni * 8 + (lid & 3) * 2;
                if (OUTH) {
                    uint32_t h0 = pack_f16x2(acc[mi][ni][1], acc[mi][ni][0]);
                    uint32_t h1 = pack_f16x2(acc[mi][ni][3], acc[mi][ni][2]);
                    *reinterpret_cast<uint32_t*>(&Ch[(size_t)row * N + col])       = h0;
                    *reinterpret_cast<uint32_t*>(&Ch[(size_t)(row + 8) * N + col]) = h1;
                } else {
                    float2 v0 = make_float2(acc[mi][ni][0], acc[mi][ni][1]);
                    float2 v1 = make_float2(acc[mi][ni][2], acc[mi][ni][3]);
                    *reinterpret_cast<float2*>(&Cf[(size_t)row * N + col])       = v0;
                    *reinterpret_cast<float2*>(&Cf[(size_t)(row + 8) * N + col]) = v1;
                }
            }
        __syncthreads();   // smem handoff before next tile's stage 0
    }
}

// ---------------------------------------------------------------------------
// Tensor-core causal flash attention, pure fp16 operands (round-14 version).
// Q, K, V, P all consumed as rounded fp16; accumulators fp32.
// CTA: 128 thr (4 warps), 64-row Q tile per CTA -> 4 CTAs/SM.
// K/V 64-row tiles, 3-stage cp.async pipeline. Softmax in log2 domain.
// ---------------------------------------------------------------------------
#define AKT_B   9216                 // 64 rows * 72 b16 * 2B
#define ASTG_B  (2 * AKT_B)          // Kh | Vh
#define ATT_SMEM (3 * ASTG_B)        // 55296 (x4 CTAs = 216KB <= 228KB)
#define SCALE_L2E 0.1803368801111204f   // 0.125 * log2(e)

__global__ __launch_bounds__(128, 4) void attn_mma(
    const __half* __restrict__ qh_g, __half* __restrict__ ch_g)
{
    extern __shared__ char smc[];
    const uint32_t abase = smem_u32(smc);
    const int tid = threadIdx.x;
    const int lid = tid & 31;
    const int wid = tid >> 5;
    const int qi  = (int)gridDim.x - 1 - (int)blockIdx.x;  // long CTAs first
    const int bh  = blockIdx.y;
    const int b   = bh >> 4;
    const int h   = bh & 15;
    const int q0  = qi * 64;
    const int bT0 = b * T_;
    const int nkt = qi + 1;

    // ---- Q fragments (fp16), loaded once from global ----
    uint32_t qfh[4][4];
    {
        const int r0 = bT0 + q0 + wid * 16 + (lid >> 2);
#pragma unroll
        for (int kc = 0; kc < 4; kc++) {
            const int c0 = h * 64 + kc * 16 + (lid & 3) * 2;
            const size_t o00 = (size_t)r0 * QKV_N + c0;
            const size_t o10 = o00 + 8 * QKV_N;
            qfh[kc][0] = *reinterpret_cast<const uint32_t*>(qh_g + o00);
            qfh[kc][1] = *reinterpret_cast<const uint32_t*>(qh_g + o10);
            qfh[kc][2] = *reinterpret_cast<const uint32_t*>(qh_g + o00 + 8);
            qfh[kc][3] = *reinterpret_cast<const uint32_t*>(qh_g + o10 + 8);
        }
    }

    float o[8][4];
#pragma unroll
    for (int j = 0; j < 8; j++)
#pragma unroll
        for (int q = 0; q < 4; q++) o[j][q] = 0.f;
    float m0r = -1e30f, m1r = -1e30f, l0r = 0.f, l1r = 0.f;

    // K/V tile loader: 2 tiles x 64 rows x 8 groups = 1024 jobs / 128 thr
#define ISSUE_KT(KT)                                                            \
    do {                                                                        \
        const uint32_t _sb = abase + ((KT) % 3) * ASTG_B;                       \
        const int _kv0 = (KT) * 64;                                             \
        _Pragma("unroll")                                                       \
        for (int _r = 0; _r < 8; _r++) {                                        \
            const int _j    = tid + _r * 128;                                   \
            const int _tile = _j >> 9;                                          \
            const int _rem  = _j & 511;                                         \
            const int _row  = _rem >> 3;                                        \
            const int _g    = _rem & 7;                                         \
            const size_t _go = (size_t)(bT0 + _kv0 + _row) * QKV_N              \
                               + C_ * (1 + _tile) + h * 64 + _g * 8;            \
            cp_async16(_sb + _tile * AKT_B + (uint32_t)(_row * 144 + _g * 16),  \
                       qh_g + _go);                                             \
        }                                                                       \
        CP_COMMIT();                                                            \
    } while (0)

    ISSUE_KT(0);
    if (nkt > 1) ISSUE_KT(1);

    const int qrow0 = q0 + wid * 16 + (lid >> 2);   // global q row (half 0)
    const int qrow1 = qrow0 + 8;

    for (int kt = 0; kt < nkt; kt++) {
        if (kt < nkt - 1) CP_WAIT1();
        else              CP_WAIT0();
        __syncthreads();
        if (kt + 2 < nkt) ISSUE_KT(kt + 2);

        const uint32_t sb = abase + (kt % 3) * ASTG_B;
        const int kv0 = kt * 64;

        // ---- S = Qh @ Kh^T ----
        float s[8][4];
#pragma unroll
        for (int jn = 0; jn < 8; jn++) {
#pragma unroll
            for (int q = 0; q < 4; q++) s[jn][q] = 0.f;
            const uint32_t aK = sb +
                (uint32_t)(((jn * 8 + (lid & 7)) * 72 + (lid >> 3) * 8) * 2);
            uint32_t khA[4], khB[4];
            ldm_x4(khA, aK);
            ldm_x4(khB, aK + 64);
            mma_f16(s[jn], qfh[0], &khA[0]);
            mma_f16(s[jn], qfh[1], &khA[2]);
            mma_f16(s[jn], qfh[2], &khB[0]);
            mma_f16(s[jn], qfh[3], &khB[2]);
        }

        // scale (log2 domain) + causal mask (diagonal ktile only)
        const bool need_mask = (kt == nkt - 1);
#pragma unroll
        for (int jn = 0; jn < 8; jn++) {
#pragma unroll
            for (int q = 0; q < 4; q++) s[jn][q] *= SCALE_L2E;
            if (need_mask) {
                const int c = kv0 + jn * 8 + (lid & 3) * 2;
                if (c > qrow0)     s[jn][0] = -1e30f;
                if (c + 1 > qrow0) s[jn][1] = -1e30f;
                if (c > qrow1)     s[jn][2] = -1e30f;
                if (c + 1 > qrow1) s[jn][3] = -1e30f;
            }
        }

        // ---- online softmax in log2 domain (rows qrow0, qrow1) ----
        float mx0 = s[0][0], mx1 = s[0][2];
#pragma unroll
        for (int jn = 0; jn < 8; jn++) {
            mx0 = fmaxf(mx0, fmaxf(s[jn][0], s[jn][1]));
            mx1 = fmaxf(mx1, fmaxf(s[jn][2], s[jn][3]));
        }
        mx0 = fmaxf(mx0, __shfl_xor_sync(0xffffffffu, mx0, 1));
        mx0 = fmaxf(mx0, __shfl_xor_sync(0xffffffffu, mx0, 2));
        mx1 = fmaxf(mx1, __shfl_xor_sync(0xffffffffu, mx1, 1));
        mx1 = fmaxf(mx1, __shfl_xor_sync(0xffffffffu, mx1, 2));
        const float mn0 = fmaxf(m0r, mx0);
        const float mn1 = fmaxf(m1r, mx1);
        const float cr0 = exp2f(m0r - mn0);
        const float cr1 = exp2f(m1r - mn1);
        float sm0 = 0.f, sm1 = 0.f;
#pragma unroll
        for (int jn = 0; jn < 8; jn++) {
            s[jn][0] = exp2f(s[jn][0] - mn0);
            s[jn][1] = exp2f(s[jn][1] - mn0);
            s[jn][2] = exp2f(s[jn][2] - mn1);
            s[jn][3] = exp2f(s[jn][3] - mn1);
            sm0 += s[jn][0] + s[jn][1];
            sm1 += s[jn][2] + s[jn][3];
        }
        sm0 += __shfl_xor_sync(0xffffffffu, sm0, 1);
        sm0 += __shfl_xor_sync(0xffffffffu, sm0, 2);
        sm1 += __shfl_xor_sync(0xffffffffu, sm1, 1);
        sm1 += __shfl_xor_sync(0xffffffffu, sm1, 2);
        l0r = l0r * cr0 + sm0;
        l1r = l1r * cr1 + sm1;
        m0r = mn0; m1r = mn1;
#pragma unroll
        for (int j = 0; j < 8; j++) {
            o[j][0] *= cr0; o[j][1] *= cr0;
            o[j][2] *= cr1; o[j][3] *= cr1;
        }

        // ---- P -> fp16 A-fragments ----
        uint32_t ph[4][4];
#pragma unroll
        for (int t = 0; t < 4; t++) {
            ph[t][0] = pack_f16x2(s[2 * t][1], s[2 * t][0]);
            ph[t][1] = pack_f16x2(s[2 * t][3], s[2 * t][2]);
            ph[t][2] = pack_f16x2(s[2 * t + 1][1], s[2 * t + 1][0]);
            ph[t][3] = pack_f16x2(s[2 * t + 1][3], s[2 * t + 1][2]);
        }

        // ---- O += Ph @ Vh ----
        const uint32_t vb = sb + AKT_B;
#pragma unroll
        for (int jp = 0; jp < 4; jp++) {
#pragma unroll
            for (int kc = 0; kc < 4; kc++) {
                const uint32_t aV = vb + (uint32_t)((
                    (kc * 16 + ((lid >> 3) & 1) * 8 + (lid & 7)) * 72 +
                    jp * 16 + (lid >> 4) * 8) * 2);
                uint32_t vh[4];
                ldm_x4_t(vh, aV);
                mma_f16(o[2 * jp],     ph[kc], &vh[0]);
                mma_f16(o[2 * jp + 1], ph[kc], &vh[2]);
            }
        }
    }
#undef ISSUE_KT

    // ---- epilogue: normalize, write ctx as fp16 ----
    const float inv0 = 1.f / l0r;
    const float inv1 = 1.f / l1r;
    const size_t r0 = (size_t)(bT0 + qrow0) * C_;
    const size_t r1 = (size_t)(bT0 + qrow1) * C_;
#pragma unroll
    for (int jn = 0; jn < 8; jn++) {
        const int col = h * 64 + jn * 8 + (lid & 3) * 2;
        float e0 = o[jn][0] * inv0, e1 = o[jn][1] * inv0;
        float e2 = o[jn][2] * inv1, e3 = o[jn][3] * inv1;
        *reinterpret_cast<uint32_t*>(&ch_g[r0 + col]) = pack_f16x2(e1, e0);
        *reinterpret_cast<uint32_t*>(&ch_g[r1 + col]) = pack_f16x2(e3, e2);
    }
}

// ---------------------------------------------------------------------------
// kernel_launch
// ---------------------------------------------------------------------------
extern "C" void kernel_launch(void* const* d_in, const int* in_sizes, int n_in,
                              void* d_out, int out_size)
{
    const float* x      = (const float*)d_in[0];  // [B,T,C]
    const float* w_qkv  = (const float*)d_in[1];  // [3C,C]
    const float* w_proj = (const float*)d_in[2];  // [C,C]
    float* out = (float*)d_out;                   // [B,T,C]

    __half *xh, *wqh, *wph, *qh, *ch;
    cudaGetSymbolAddress((void**)&xh,  g_xh);
    cudaGetSymbolAddress((void**)&wqh, g_wqh);
    cudaGetSymbolAddress((void**)&wph, g_wph);
    cudaGetSymbolAddress((void**)&qh,  g_qh);
    cudaGetSymbolAddress((void**)&ch,  g_ch);

    cudaFuncSetAttribute(gemm_mma_f16<true>,
                         cudaFuncAttributeMaxDynamicSharedMemorySize, GEMM_SMEM);
    cudaFuncSetAttribute(gemm_mma_f16<false>,
                         cudaFuncAttributeMaxDynamicSharedMemorySize, GEMM_SMEM);
    cudaFuncSetAttribute(attn_mma,
                         cudaFuncAttributeMaxDynamicSharedMemorySize, ATT_SMEM);

    // Fused convert (one launch)
    prep_f16<<<(PREP_JOBS + 255) / 256, 256>>>(x, w_qkv, w_proj, xh, wqh, wph);

    // 1) QKV projection (persistent single-pass fp16) -> qh
    gemm_mma_f16<true><<<GEMM_GRID, 256, GEMM_SMEM>>>(
        xh, wqh, nullptr, qh, M_, QKV_N, C_);

    // 2) Tensor-core causal flash attention -> ch (fp16)
    dim3 g2(T_ / 64, B_ * H_);
    attn_mma<<<g2, 128, ATT_SMEM>>>(qh, ch);

    // 3) Output projection (persistent single-pass fp16) -> fp32 out
    gemm_mma_f16<false><<<GEMM_GRID, 256, GEMM_SMEM>>>(
        ch, wph, out, nullptr, M_, C_, C_);
}

// round 17
// speedup vs baseline: 1.0118x; 1.0118x over previous
#include <cuda_runtime.h>
#include <cuda_fp16.h>
#include <cstdint>

// Problem constants
#define B_  4
#define T_  2048
#define C_  1024
#define H_  16
#define D_  64
#define M_  (B_ * T_)       // 8192 rows
#define QKV_N (3 * C_)      // 3072

// ---------------------------------------------------------------------------
// Scratch (device globals; no runtime allocation allowed)
// ---------------------------------------------------------------------------
__device__ __half g_xh[(size_t)M_ * C_];
__device__ __half g_wqh[(size_t)QKV_N * C_];
__device__ __half g_wph[(size_t)C_ * C_];
__device__ __half g_qh[(size_t)M_ * QKV_N];
__device__ __half g_ch[(size_t)M_ * C_];

// ---------------------------------------------------------------------------
// PTX helpers (all non-arch-gated sm_80/sm_90 instructions)
// ---------------------------------------------------------------------------
__device__ __forceinline__ uint32_t smem_u32(const void* p) {
    uint32_t a;
    asm("{ .reg .u64 t; cvta.to.shared.u64 t, %1; cvt.u32.u64 %0, t; }"
        : "=r"(a) : "l"(p));
    return a;
}
__device__ __forceinline__ void cp_async16(uint32_t s, const void* g) {
    asm volatile("cp.async.cg.shared.global [%0], [%1], 16;"
                 :: "r"(s), "l"(g) : "memory");
}
#define CP_COMMIT() asm volatile("cp.async.commit_group;" ::: "memory")
#define CP_WAIT0()  asm volatile("cp.async.wait_group 0;" ::: "memory")
#define CP_WAIT1()  asm volatile("cp.async.wait_group 1;" ::: "memory")

__device__ __forceinline__ void ldm_x4(uint32_t* r, uint32_t a) {
    asm volatile("ldmatrix.sync.aligned.m8n8.x4.shared.b16 {%0,%1,%2,%3}, [%4];"
        : "=r"(r[0]), "=r"(r[1]), "=r"(r[2]), "=r"(r[3]) : "r"(a));
}
__device__ __forceinline__ void ldm_x4_t(uint32_t* r, uint32_t a) {
    asm volatile("ldmatrix.sync.aligned.m8n8.x4.trans.shared.b16 {%0,%1,%2,%3}, [%4];"
        : "=r"(r[0]), "=r"(r[1]), "=r"(r[2]), "=r"(r[3]) : "r"(a));
}
__device__ __forceinline__ void mma_f16(float* d, const uint32_t* a, const uint32_t* b) {
    asm volatile(
        "mma.sync.aligned.m16n8k16.row.col.f32.f16.f16.f32 "
        "{%0,%1,%2,%3}, {%4,%5,%6,%7}, {%8,%9}, {%0,%1,%2,%3};"
        : "+f"(d[0]), "+f"(d[1]), "+f"(d[2]), "+f"(d[3])
        : "r"(a[0]), "r"(a[1]), "r"(a[2]), "r"(a[3]), "r"(b[0]), "r"(b[1]));
}
// pack two f32 -> f16x2 ({hi -> upper16, lo -> lower16})
__device__ __forceinline__ uint32_t pack_f16x2(float hi, float lo) {
    uint32_t d;
    asm("cvt.rn.f16x2.f32 %0, %1, %2;" : "=r"(d) : "f"(hi), "f"(lo));
    return d;
}

// ---------------------------------------------------------------------------
// Fused prep: convert x, w_qkv, w_proj to fp16 in ONE launch.
// ---------------------------------------------------------------------------
#define NX_JOBS  (M_ * C_ / 4)
#define NWQ_JOBS (QKV_N * C_ / 4)
#define NWP_JOBS (C_ * C_ / 4)
#define PREP_JOBS (NX_JOBS + NWQ_JOBS + NWP_JOBS)

__global__ __launch_bounds__(256) void prep_f16(
    const float* __restrict__ x, const float* __restrict__ wq,
    const float* __restrict__ wp,
    __half* __restrict__ xh, __half* __restrict__ wqh, __half* __restrict__ wph)
{
    int i = blockIdx.x * blockDim.x + threadIdx.x;
    if (i >= PREP_JOBS) return;
    const float* src;
    __half* dst;
    int j;
    if (i < NX_JOBS)                    { src = x;  dst = xh;  j = i; }
    else if (i < NX_JOBS + NWQ_JOBS)    { src = wq; dst = wqh; j = i - NX_JOBS; }
    else                                { src = wp; dst = wph; j = i - NX_JOBS - NWQ_JOBS; }
    float4 v = reinterpret_cast<const float4*>(src)[j];
    reinterpret_cast<uint2*>(dst)[j] =
        make_uint2(pack_f16x2(v.y, v.x), pack_f16x2(v.w, v.z));
}

// ---------------------------------------------------------------------------
// mma.sync fp16 GEMM: C[M,N] = Ah[M,K] @ Bh[N,K]^T (single pass).
// 128x128 CTA tile, BK=64, 8 warps (2x4), warp tile 64x32.
// 3-stage cp.async pipeline (wait_group 1 steady state); 2 CTAs/SM.
// OUTH=true: write fp16; else fp32.
// ---------------------------------------------------------------------------
#define TILE_B  18432                   // 128 rows * 72 b16 * 2B
#define STAGE_B (2 * TILE_B)            // 36864
#define GEMM_SMEM (3 * STAGE_B)         // 110592 (x2 CTAs = 221KB <= 228KB)

template <bool OUTH>
__global__ __launch_bounds__(256, 2) void gemm_mma_f16(
    const __half* __restrict__ Ah, const __half* __restrict__ Bh,
    float* __restrict__ Cf, __half* __restrict__ Ch, int M, int N, int K)
{
    extern __shared__ char smc[];
    const uint32_t sbase = smem_u32(smc);
    const int tid = threadIdx.x;
    const int lid = tid & 31;
    const int wid = tid >> 5;
    const int wm  = wid >> 2;
    const int wn  = wid & 3;
    const int m0  = blockIdx.y * 128;
    const int n0  = blockIdx.x * 128;

    float acc[4][4][4];
#pragma unroll
    for (int i = 0; i < 4; i++)
#pragma unroll
        for (int j = 0; j < 4; j++)
#pragma unroll
            for (int q = 0; q < 4; q++) acc[i][j][q] = 0.f;

    const int a_base = (wm * 64 + (lid & 15)) * 72 + ((lid >> 4) * 8);
    const int b_base = (wn * 32 + (lid & 7) + ((lid >> 4) * 8)) * 72 +
                       (((lid >> 3) & 1) * 8);
    const int NS = K / 64;

#define ISSUE_STAGE(S)                                                          \
    do {                                                                        \
        const int _kc = (S) * 64;                                               \
        const uint32_t _sb = sbase + ((S) % 3) * STAGE_B;                       \
        _Pragma("unroll")                                                       \
        for (int _r = 0; _r < 4; _r++) {                                        \
            const int _c   = tid + _r * 256;                                    \
            const int _row = _c >> 3;                                           \
            const int _c8  = (_c & 7) * 8;                                      \
            const uint32_t _so = _sb + (uint32_t)((_row * 72 + _c8) * 2);       \
            cp_async16(_so,          Ah + (size_t)(m0 + _row) * K + _kc + _c8); \
            cp_async16(_so + TILE_B, Bh + (size_t)(n0 + _row) * K + _kc + _c8); \
        }                                                                       \
        CP_COMMIT();                                                            \
    } while (0)

    ISSUE_STAGE(0);
    ISSUE_STAGE(1);

    for (int s = 0; s < NS; s++) {
        if (s < NS - 1) CP_WAIT1();
        else            CP_WAIT0();
        __syncthreads();
        if (s + 2 < NS) ISSUE_STAGE(s + 2);

        const uint32_t sb = sbase + (s % 3) * STAGE_B;
#pragma unroll
        for (int ks = 0; ks < 4; ks++) {
            uint32_t ah[4][4], b01[4], b23[4];
#pragma unroll
            for (int mi = 0; mi < 4; mi++) {
                const uint32_t ao = sb +
                    (uint32_t)((a_base + mi * 16 * 72 + ks * 16) * 2);
                ldm_x4(ah[mi], ao);
            }
            {
                const uint32_t bo = sb + TILE_B +
                    (uint32_t)((b_base + ks * 16) * 2);
                ldm_x4(b01, bo);
                ldm_x4(b23, bo + 16 * 72 * 2);
            }
#pragma unroll
            for (int mi = 0; mi < 4; mi++) {
                mma_f16(acc[mi][0], ah[mi], &b01[0]);
                mma_f16(acc[mi][1], ah[mi], &b01[2]);
                mma_f16(acc[mi][2], ah[mi], &b23[0]);
                mma_f16(acc[mi][3], ah[mi], &b23[2]);
            }
        }
    }
#undef ISSUE_STAGE

#pragma unroll
    for (int mi = 0; mi < 4; mi++)
#pragma unroll
        for (int ni = 0; ni < 4; ni++) {
            const int row = m0 + wm * 64 + mi * 16 + (lid >> 2);
            const int col = n0 + wn * 32 + ni * 8 + (lid & 3) * 2;
            if (OUTH) {
                uint32_t h0 = pack_f16x2(acc[mi][ni][1], acc[mi][ni][0]);
                uint32_t h1 = pack_f16x2(acc[mi][ni][3], acc[mi][ni][2]);
                *reinterpret_cast<uint32_t*>(&Ch[(size_t)row * N + col])       = h0;
                *reinterpret_cast<uint32_t*>(&Ch[(size_t)(row + 8) * N + col]) = h1;
            } else {
                float2 v0 = make_float2(acc[mi][ni][0], acc[mi][ni][1]);
                float2 v1 = make_float2(acc[mi][ni][2], acc[mi][ni][3]);
                *reinterpret_cast<float2*>(&Cf[(size_t)row * N + col])       = v0;
                *reinterpret_cast<float2*>(&Cf[(size_t)(row + 8) * N + col]) = v1;
            }
        }
}

// ---------------------------------------------------------------------------
// Tensor-core causal flash attention, pure fp16 operands (round-14 config).
// Q, K, V, P all consumed as rounded fp16; accumulators fp32.
// CTA: 128 thr (4 warps), 64-row Q tile per CTA -> 4 CTAs/SM.
// K/V 64-row tiles, 3-stage cp.async pipeline. Softmax in log2 domain.
// ---------------------------------------------------------------------------
#define AKT_B   9216                 // 64 rows * 72 b16 * 2B
#define ASTG_B  (2 * AKT_B)          // Kh | Vh
#define ATT_SMEM (3 * ASTG_B)        // 55296 (x4 CTAs = 216KB <= 228KB)
#define SCALE_L2E 0.1803368801111204f   // 0.125 * log2(e)

__global__ __launch_bounds__(128, 4) void attn_mma(
    const __half* __restrict__ qh_g, __half* __restrict__ ch_g)
{
    extern __shared__ char smc[];
    const uint32_t abase = smem_u32(smc);
    const int tid = threadIdx.x;
    const int lid = tid & 31;
    const int wid = tid >> 5;
    const int qi  = (int)gridDim.x - 1 - (int)blockIdx.x;  // long CTAs first
    const int bh  = blockIdx.y;
    const int b   = bh >> 4;
    const int h   = bh & 15;
    const int q0  = qi * 64;
    const int bT0 = b * T_;
    const int nkt = qi + 1;

    // ---- Q fragments (fp16), loaded once from global ----
    uint32_t qfh[4][4];
    {
        const int r0 = bT0 + q0 + wid * 16 + (lid >> 2);
#pragma unroll
        for (int kc = 0; kc < 4; kc++) {
            const int c0 = h * 64 + kc * 16 + (lid & 3) * 2;
            const size_t o00 = (size_t)r0 * QKV_N + c0;
            const size_t o10 = o00 + 8 * QKV_N;
            qfh[kc][0] = *reinterpret_cast<const uint32_t*>(qh_g + o00);
            qfh[kc][1] = *reinterpret_cast<const uint32_t*>(qh_g + o10);
            qfh[kc][2] = *reinterpret_cast<const uint32_t*>(qh_g + o00 + 8);
            qfh[kc][3] = *reinterpret_cast<const uint32_t*>(qh_g + o10 + 8);
        }
    }

    float o[8][4];
#pragma unroll
    for (int j = 0; j < 8; j++)
#pragma unroll
        for (int q = 0; q < 4; q++) o[j][q] = 0.f;
    float m0r = -1e30f, m1r = -1e30f, l0r = 0.f, l1r = 0.f;

    // K/V tile loader: 2 tiles x 64 rows x 8 groups = 1024 jobs / 128 thr
#define ISSUE_KT(KT)                                                            \
    do {                                                                        \
        const uint32_t _sb = abase + ((KT) % 3) * ASTG_B;                       \
        const int _kv0 = (KT) * 64;                                             \
        _Pragma("unroll")                                                       \
        for (int _r = 0; _r < 8; _r++) {                                        \
            const int _j    = tid + _r * 128;                                   \
            const int _tile = _j >> 9;                                          \
            const int _rem  = _j & 511;                                         \
            const int _row  = _rem >> 3;                                        \
            const int _g    = _rem & 7;                                         \
            const size_t _go = (size_t)(bT0 + _kv0 + _row) * QKV_N              \
                               + C_ * (1 + _tile) + h * 64 + _g * 8;            \
            cp_async16(_sb + _tile * AKT_B + (uint32_t)(_row * 144 + _g * 16),  \
                       qh_g + _go);                                             \
        }                                                                       \
        CP_COMMIT();                                                            \
    } while (0)

    ISSUE_KT(0);
    if (nkt > 1) ISSUE_KT(1);

    const int qrow0 = q0 + wid * 16 + (lid >> 2);   // global q row (half 0)
    const int qrow1 = qrow0 + 8;

    for (int kt = 0; kt < nkt; kt++) {
        if (kt < nkt - 1) CP_WAIT1();
        else              CP_WAIT0();
        __syncthreads();
        if (kt + 2 < nkt) ISSUE_KT(kt + 2);

        const uint32_t sb = abase + (kt % 3) * ASTG_B;
        const int kv0 = kt * 64;

        // ---- S = Qh @ Kh^T ----
        float s[8][4];
#pragma unroll
        for (int jn = 0; jn < 8; jn++) {
#pragma unroll
            for (int q = 0; q < 4; q++) s[jn][q] = 0.f;
            const uint32_t aK = sb +
                (uint32_t)(((jn * 8 + (lid & 7)) * 72 + (lid >> 3) * 8) * 2);
            uint32_t khA[4], khB[4];
            ldm_x4(khA, aK);
            ldm_x4(khB, aK + 64);
            mma_f16(s[jn], qfh[0], &khA[0]);
            mma_f16(s[jn], qfh[1], &khA[2]);
            mma_f16(s[jn], qfh[2], &khB[0]);
            mma_f16(s[jn], qfh[3], &khB[2]);
        }

        // scale (log2 domain) + causal mask (diagonal ktile only)
        const bool need_mask = (kt == nkt - 1);
#pragma unroll
        for (int jn = 0; jn < 8; jn++) {
#pragma unroll
            for (int q = 0; q < 4; q++) s[jn][q] *= SCALE_L2E;
            if (need_mask) {
                const int c = kv0 + jn * 8 + (lid & 3) * 2;
                if (c > qrow0)     s[jn][0] = -1e30f;
                if (c + 1 > qrow0) s[jn][1] = -1e30f;
                if (c > qrow1)     s[jn][2] = -1e30f;
                if (c + 1 > qrow1) s[jn][3] = -1e30f;
            }
        }

        // ---- online softmax in log2 domain (rows qrow0, qrow1) ----
        float mx0 = s[0][0], mx1 = s[0][2];
#pragma unroll
        for (int jn = 0; jn < 8; jn++) {
            mx0 = fmaxf(mx0, fmaxf(s[jn][0], s[jn][1]));
            mx1 = fmaxf(mx1, fmaxf(s[jn][2], s[jn][3]));
        }
        mx0 = fmaxf(mx0, __shfl_xor_sync(0xffffffffu, mx0, 1));
        mx0 = fmaxf(mx0, __shfl_xor_sync(0xffffffffu, mx0, 2));
        mx1 = fmaxf(mx1, __shfl_xor_sync(0xffffffffu, mx1, 1));
        mx1 = fmaxf(mx1, __shfl_xor_sync(0xffffffffu, mx1, 2));
        const float mn0 = fmaxf(m0r, mx0);
        const float mn1 = fmaxf(m1r, mx1);
        const float cr0 = exp2f(m0r - mn0);
        const float cr1 = exp2f(m1r - mn1);
        float sm0 = 0.f, sm1 = 0.f;
#pragma unroll
        for (int jn = 0; jn < 8; jn++) {
            s[jn][0] = exp2f(s[jn][0] - mn0);
            s[jn][1] = exp2f(s[jn][1] - mn0);
            s[jn][2] = exp2f(s[jn][2] - mn1);
            s[jn][3] = exp2f(s[jn][3] - mn1);
            sm0 += s[jn][0] + s[jn][1];
            sm1 += s[jn][2] + s[jn][3];
        }
        sm0 += __shfl_xor_sync(0xffffffffu, sm0, 1);
        sm0 += __shfl_xor_sync(0xffffffffu, sm0, 2);
        sm1 += __shfl_xor_sync(0xffffffffu, sm1, 1);
        sm1 += __shfl_xor_sync(0xffffffffu, sm1, 2);
        l0r = l0r * cr0 + sm0;
        l1r = l1r * cr1 + sm1;
        m0r = mn0; m1r = mn1;
#pragma unroll
        for (int j = 0; j < 8; j++) {
            o[j][0] *= cr0; o[j][1] *= cr0;
            o[j][2] *= cr1; o[j][3] *= cr1;
        }

        // ---- P -> fp16 A-fragments ----
        uint32_t ph[4][4];
#pragma unroll
        for (int t = 0; t < 4; t++) {
            ph[t][0] = pack_f16x2(s[2 * t][1], s[2 * t][0]);
            ph[t][1] = pack_f16x2(s[2 * t][3], s[2 * t][2]);
            ph[t][2] = pack_f16x2(s[2 * t + 1][1], s[2 * t + 1][0]);
            ph[t][3] = pack_f16x2(s[2 * t + 1][3], s[2 * t + 1][2]);
        }

        // ---- O += Ph @ Vh ----
        const uint32_t vb = sb + AKT_B;
#pragma unroll
        for (int jp = 0; jp < 4; jp++) {
#pragma unroll
            for (int kc = 0; kc < 4; kc++) {
                const uint32_t aV = vb + (uint32_t)((
                    (kc * 16 + ((lid >> 3) & 1) * 8 + (lid & 7)) * 72 +
                    jp * 16 + (lid >> 4) * 8) * 2);
                uint32_t vh[4];
                ldm_x4_t(vh, aV);
                mma_f16(o[2 * jp],     ph[kc], &vh[0]);
                mma_f16(o[2 * jp + 1], ph[kc], &vh[2]);
            }
        }
    }
#undef ISSUE_KT

    // ---- epilogue: normalize, write ctx as fp16 ----
    const float inv0 = 1.f / l0r;
    const float inv1 = 1.f / l1r;
    const size_t r0 = (size_t)(bT0 + qrow0) * C_;
    const size_t r1 = (size_t)(bT0 + qrow1) * C_;
#pragma unroll
    for (int jn = 0; jn < 8; jn++) {
        const int col = h * 64 + jn * 8 + (lid & 3) * 2;
        float e0 = o[jn][0] * inv0, e1 = o[jn][1] * inv0;
        float e2 = o[jn][2] * inv1, e3 = o[jn][3] * inv1;
        *reinterpret_cast<uint32_t*>(&ch_g[r0 + col]) = pack_f16x2(e1, e0);
        *reinterpret_cast<uint32_t*>(&ch_g[r1 + col]) = pack_f16x2(e3, e2);
    }
}

// ---------------------------------------------------------------------------
// kernel_launch
// ---------------------------------------------------------------------------
extern "C" void kernel_launch(void* const* d_in, const int* in_sizes, int n_in,
                              void* d_out, int out_size)
{
    const float* x      = (const float*)d_in[0];  // [B,T,C]
    const float* w_qkv  = (const float*)d_in[1];  // [3C,C]
    const float* w_proj = (const float*)d_in[2];  // [C,C]
    float* out = (float*)d_out;                   // [B,T,C]

    __half *xh, *wqh, *wph, *qh, *ch;
    cudaGetSymbolAddress((void**)&xh,  g_xh);
    cudaGetSymbolAddress((void**)&wqh, g_wqh);
    cudaGetSymbolAddress((void**)&wph, g_wph);
    cudaGetSymbolAddress((void**)&qh,  g_qh);
    cudaGetSymbolAddress((void**)&ch,  g_ch);

    cudaFuncSetAttribute(gemm_mma_f16<true>,
                         cudaFuncAttributeMaxDynamicSharedMemorySize, GEMM_SMEM);
    cudaFuncSetAttribute(gemm_mma_f16<false>,
                         cudaFuncAttributeMaxDynamicSharedMemorySize, GEMM_SMEM);
    cudaFuncSetAttribute(attn_mma,
                         cudaFuncAttributeMaxDynamicSharedMemorySize, ATT_SMEM);

    // Fused convert (one launch)
    prep_f16<<<(PREP_JOBS + 255) / 256, 256>>>(x, w_qkv, w_proj, xh, wqh, wph);

    // 1) QKV projection (single-pass fp16) -> qh
    dim3 g1(QKV_N / 128, M_ / 128);
    gemm_mma_f16<true><<<g1, 256, GEMM_SMEM>>>(
        xh, wqh, nullptr, qh, M_, QKV_N, C_);

    // 2) Tensor-core causal flash attention -> ch (fp16)
    dim3 g2(T_ / 64, B_ * H_);
    attn_mma<<<g2, 128, ATT_SMEM>>>(qh, ch);

    // 3) Output projection (single-pass fp16) -> fp32 out
    dim3 g3(C_ / 128, M_ / 128);
    gemm_mma_f16<false><<<g3, 256, GEMM_SMEM>>>(
        ch, wph, out, nullptr, M_, C_, C_);
}